// round 7
// baseline (speedup 1.0000x reference)
#include <cuda_runtime.h>
#include <cuda_bf16.h>
#include <cstdint>

#define SEQ    4096
#define DM     1024
#define NOUT   864      // 12 * 72
#define NIMU   72
#define TSTEPS 300
#define PLANE  (NIMU*SEQ)   // 294912

// GEMM tiling (mma.sync m16n8k16 bf16)
#define BM     128
#define BN     96
#define BK     32
#define NIT    (DM/BK)          // 32 k-chunks
#define APITCH 80               // 32 bf16 = 64B, padded to 80B (conflict-free ldmatrix)
#define R_AHI  0
#define R_ALO  (128*APITCH)                 // 10240
#define R_BHI  (2*128*APITCH)               // 20480
#define R_BLO  (2*128*APITCH + 96*APITCH)   // 28160
#define STAGE  (R_BLO + 96*APITCH)          // 35840
#define SMEM_TOT (3*STAGE)                  // 107520 (3-stage ring)
#define NCOPY  1792   // 16B cp.async per stage: A 2*512 + B 2*384

typedef unsigned long long ull;

// -------- scratch (static device memory; no runtime allocs) --------
__device__ __align__(16) __nv_bfloat16 g_ahi[SEQ * DM];     // LN output hi
__device__ __align__(16) __nv_bfloat16 g_alo[SEQ * DM];     // LN output lo
__device__ __align__(16) __nv_bfloat16 g_whi[NOUT * DM];    // W^T hi
__device__ __align__(16) __nv_bfloat16 g_wlo[NOUT * DM];    // W^T lo
__device__ __align__(16) float g_pT [NOUT * SEQ];           // GEMM output, TRANSPOSED [n][s]

// ======================= PTX helpers ===============================
__device__ __forceinline__ uint32_t smem_to_u32(const void* p) {
    uint32_t a;
    asm("{ .reg .u64 t; cvta.to.shared.u64 t, %1; cvt.u32.u64 %0, t; }" : "=r"(a) : "l"(p));
    return a;
}
#define CP_COMMIT() asm volatile("cp.async.commit_group;" ::: "memory")
#define CP_WAIT1()  asm volatile("cp.async.wait_group 1;" ::: "memory")
__device__ __forceinline__ void cpasync16(uint32_t dst, const void* src) {
    asm volatile("cp.async.cg.shared.global [%0], [%1], 16;" :: "r"(dst), "l"(src) : "memory");
}
#define LDSM_X4(r0, r1, r2, r3, addr) \
    asm volatile("ldmatrix.sync.aligned.m8n8.x4.shared.b16 {%0,%1,%2,%3}, [%4];" \
                 : "=r"(r0), "=r"(r1), "=r"(r2), "=r"(r3) : "r"(addr))
#define MMA16816(d, a, b) \
    asm volatile("mma.sync.aligned.m16n8k16.row.col.f32.bf16.bf16.f32 " \
                 "{%0,%1,%2,%3}, {%4,%5,%6,%7}, {%8,%9}, {%0,%1,%2,%3};" \
                 : "+f"((d)[0]), "+f"((d)[1]), "+f"((d)[2]), "+f"((d)[3]) \
                 : "r"((a)[0]), "r"((a)[1]), "r"((a)[2]), "r"((a)[3]), \
                   "r"((b)[0]), "r"((b)[1]))

__device__ __forceinline__ ull ffma2(ull a, ull b, ull c) {
    ull d; asm("fma.rn.f32x2 %0, %1, %2, %3;" : "=l"(d) : "l"(a), "l"(b), "l"(c)); return d;
}
__device__ __forceinline__ ull fmul2(ull a, ull b) {
    ull d; asm("mul.rn.f32x2 %0, %1, %2;" : "=l"(d) : "l"(a), "l"(b)); return d;
}
__device__ __forceinline__ ull fadd2(ull a, ull b) {
    ull d; asm("add.rn.f32x2 %0, %1, %2;" : "=l"(d) : "l"(a), "l"(b)); return d;
}
__device__ __forceinline__ ull fpack2(float lo, float hi) {
    ull d; asm("mov.b64 %0, {%1, %2};" : "=l"(d) : "f"(lo), "f"(hi)); return d;
}
__device__ __forceinline__ ull lds64_vol(uint32_t addr) {
    ull v; asm volatile("ld.volatile.shared.b64 %0, [%1];" : "=l"(v) : "r"(addr)); return v;
}
__device__ __forceinline__ void sts64_vol(uint32_t addr, ull v) {
    asm volatile("st.volatile.shared.b64 [%0], %1;" :: "r"(addr), "l"(v));
}
__device__ __forceinline__ float softplusf(float x) {
    return fmaxf(x, 0.0f) + log1pf(expf(-fabsf(x)));
}

// ======================= zero kinematics ===========================
__global__ void zero_kernel(float* __restrict__ out) {
    int i = blockIdx.x * blockDim.x + threadIdx.x;   // PLANE/4 threads
    ((float4*)out)[i] = make_float4(0.f, 0.f, 0.f, 0.f);
}

// ============== Fused LayerNorm + W-transpose ======================
// blocks [0, SEQ): LN row -> bf16 hi/lo split of xn
// blocks [SEQ, SEQ+864): 32x32 W transpose tile -> bf16 hi/lo W^T
__global__ __launch_bounds__(256) void prep_kernel(const float* __restrict__ hs,
                                                   const float* __restrict__ gamma,
                                                   const float* __restrict__ beta,
                                                   const float* __restrict__ W) {
    int tid = threadIdx.x;
    if (blockIdx.x < SEQ) {
        int row = blockIdx.x;
        const float4* xr = (const float4*)(hs + (size_t)row * DM);
        float4 v = xr[tid];
        float s  = v.x + v.y + v.z + v.w;
        float ss = v.x*v.x + v.y*v.y + v.z*v.z + v.w*v.w;
        #pragma unroll
        for (int o = 16; o > 0; o >>= 1) {
            s  += __shfl_xor_sync(0xffffffffu, s,  o);
            ss += __shfl_xor_sync(0xffffffffu, ss, o);
        }
        __shared__ float2 part[8];
        __shared__ float2 mv;
        int w = tid >> 5, l = tid & 31;
        if (l == 0) part[w] = make_float2(s, ss);
        __syncthreads();
        if (tid == 0) {
            float S = 0.f, SS = 0.f;
            #pragma unroll
            for (int i = 0; i < 8; ++i) { S += part[i].x; SS += part[i].y; }
            float mu  = S * (1.0f / DM);
            float var = SS * (1.0f / DM) - mu * mu;
            mv = make_float2(mu, rsqrtf(var + 1e-5f));
        }
        __syncthreads();
        float mu = mv.x, rstd = mv.y;
        float4 g  = ((const float4*)gamma)[tid];
        float4 be = ((const float4*)beta)[tid];
        float o0 = (v.x - mu) * rstd * g.x + be.x;
        float o1 = (v.y - mu) * rstd * g.y + be.y;
        float o2 = (v.z - mu) * rstd * g.z + be.z;
        float o3 = (v.w - mu) * rstd * g.w + be.w;

        __nv_bfloat16 h0 = __float2bfloat16_rn(o0), h1 = __float2bfloat16_rn(o1);
        __nv_bfloat16 h2 = __float2bfloat16_rn(o2), h3 = __float2bfloat16_rn(o3);
        __nv_bfloat16 l0 = __float2bfloat16_rn(o0 - __bfloat162float(h0));
        __nv_bfloat16 l1 = __float2bfloat16_rn(o1 - __bfloat162float(h1));
        __nv_bfloat16 l2 = __float2bfloat16_rn(o2 - __bfloat162float(h2));
        __nv_bfloat16 l3 = __float2bfloat16_rn(o3 - __bfloat162float(h3));

        __nv_bfloat162* ph = (__nv_bfloat162*)(g_ahi + (size_t)row * DM);
        __nv_bfloat162* pl = (__nv_bfloat162*)(g_alo + (size_t)row * DM);
        __nv_bfloat162 a, b2;
        a.x = h0; a.y = h1; b2.x = h2; b2.y = h3;
        ph[2*tid] = a; ph[2*tid+1] = b2;
        a.x = l0; a.y = l1; b2.x = l2; b2.y = l3;
        pl[2*tid] = a; pl[2*tid+1] = b2;
    } else {
        __shared__ float tile[32][33];
        int b2 = blockIdx.x - SEQ;                 // 0..863 (27 x 32 tiles)
        int n0 = (b2 % 27) * 32, k0 = (b2 / 27) * 32;
        int tx = tid & 31, ty = tid >> 5;          // 32 x 8
        #pragma unroll
        for (int j = 0; j < 4; ++j)
            tile[ty + 8*j][tx] = W[(size_t)(k0 + ty + 8*j) * NOUT + n0 + tx];
        __syncthreads();
        #pragma unroll
        for (int j = 0; j < 4; ++j) {
            float v = tile[tx][ty + 8*j];
            __nv_bfloat16 h = __float2bfloat16_rn(v);
            size_t o = (size_t)(n0 + ty + 8*j) * DM + k0 + tx;
            g_whi[o] = h;
            g_wlo[o] = __float2bfloat16_rn(v - __bfloat162float(h));
        }
    }
}

// ================ mma.sync bf16-split GEMM =========================
// g_pT[n][s] = (Ahi*Bhi + Alo*Bhi + Ahi*Blo)[s][n] + bias[n]
// 8 warps: warp grid 4(m) x 2(n); warp tile 32m x 48n; k16 per HMMA.
// At the legacy-HMMA structural ceiling (~53% tensor) — do not touch.
__global__ __launch_bounds__(256, 2) void gemm_kernel(const float* __restrict__ bias) {
    extern __shared__ char smem[];
    uint32_t sb = smem_to_u32(smem);
    int tid = threadIdx.x, wid = tid >> 5, lane = tid & 31;
    int n0 = blockIdx.x * BN, m0 = blockIdx.y * BM;

    auto stage = [&](int ch, int s) {
        uint32_t base = sb + s * STAGE;
        int kb = ch * BK;
        #pragma unroll
        for (int v = 0; v < NCOPY / 256; ++v) {
            int idx = tid + v * 256;
            const void* src; uint32_t off;
            if (idx < 1024) {                       // A: 2 mats x 128 rows x 4 vec16
                int mat = idx >> 9;
                int i = idx & 511;
                int r = i >> 2, c = i & 3;
                const __nv_bfloat16* g = mat ? g_alo : g_ahi;
                src = g + (size_t)(m0 + r) * DM + kb + c * 8;
                off = (mat ? R_ALO : R_AHI) + r * APITCH + c * 16;
            } else {                                // B: 2 mats x 96 rows x 4 vec16
                int b = idx - 1024;
                int mat = b / 384; int rb = b - mat * 384;
                int r = rb >> 2, c = rb & 3;
                const __nv_bfloat16* g = mat ? g_wlo : g_whi;
                src = g + (size_t)(n0 + r) * DM + kb + c * 8;
                off = (mat ? R_BLO : R_BHI) + r * APITCH + c * 16;
            }
            cpasync16(base + off, src);
        }
        CP_COMMIT();
    };

    stage(0, 0);
    stage(1, 1);

    int wm = (wid >> 1) * 32;
    int wn = (wid & 1) * 48;
    uint32_t aoff = (uint32_t)(wm + (lane & 15)) * APITCH + (uint32_t)(lane >> 4) * 16;
    uint32_t boff = (uint32_t)(wn + (lane & 7) + ((lane >> 4) & 1) * 8) * APITCH
                  + (uint32_t)((lane >> 3) & 1) * 16;

    float acc[2][6][4];
    #pragma unroll
    for (int i = 0; i < 2; ++i)
        #pragma unroll
        for (int j = 0; j < 6; ++j)
            #pragma unroll
            for (int q = 0; q < 4; ++q) acc[i][j][q] = 0.f;

    int slot = 0, nslot = 2;
    for (int it = 0; it < NIT; ++it) {
        CP_WAIT1();
        __syncthreads();
        if (it + 2 < NIT) stage(it + 2, nslot);
        uint32_t base = sb + slot * STAGE;
        #pragma unroll
        for (int ki = 0; ki < 2; ++ki) {
            uint32_t ah[2][4], al[2][4], bh[6][2], bl[6][2];
            uint32_t ka = base + ki * 32 + aoff;
            LDSM_X4(ah[0][0], ah[0][1], ah[0][2], ah[0][3], ka + R_AHI);
            LDSM_X4(ah[1][0], ah[1][1], ah[1][2], ah[1][3], ka + R_AHI + 16 * APITCH);
            LDSM_X4(al[0][0], al[0][1], al[0][2], al[0][3], ka + R_ALO);
            LDSM_X4(al[1][0], al[1][1], al[1][2], al[1][3], ka + R_ALO + 16 * APITCH);
            uint32_t kb2 = base + ki * 32 + boff;
            #pragma unroll
            for (int pj = 0; pj < 3; ++pj) {
                LDSM_X4(bh[2*pj][0], bh[2*pj][1], bh[2*pj+1][0], bh[2*pj+1][1],
                        kb2 + R_BHI + pj * 16 * APITCH);
                LDSM_X4(bl[2*pj][0], bl[2*pj][1], bl[2*pj+1][0], bl[2*pj+1][1],
                        kb2 + R_BLO + pj * 16 * APITCH);
            }
            #pragma unroll
            for (int mi = 0; mi < 2; ++mi)
                #pragma unroll
                for (int nj = 0; nj < 6; ++nj)
                    MMA16816(acc[mi][nj], ah[mi], bh[nj]);
            #pragma unroll
            for (int mi = 0; mi < 2; ++mi)
                #pragma unroll
                for (int nj = 0; nj < 6; ++nj)
                    MMA16816(acc[mi][nj], al[mi], bh[nj]);
            #pragma unroll
            for (int mi = 0; mi < 2; ++mi)
                #pragma unroll
                for (int nj = 0; nj < 6; ++nj)
                    MMA16816(acc[mi][nj], ah[mi], bl[nj]);
        }
        slot = (slot == 2) ? 0 : slot + 1;
        nslot = (nslot == 2) ? 0 : nslot + 1;
    }

    // ---- epilogue: frags -> g_pT (transposed, +bias) ----
    int qr = lane >> 2, qc = (lane & 3) * 2;
    #pragma unroll
    for (int mi = 0; mi < 2; ++mi) {
        int m = m0 + wm + mi * 16 + qr;
        #pragma unroll
        for (int nj = 0; nj < 6; ++nj) {
            int n = n0 + wn + nj * 8 + qc;
            float b0 = bias[n], b1 = bias[n + 1];
            g_pT[(size_t)n       * SEQ + m]     = acc[mi][nj][0] + b0;
            g_pT[(size_t)(n + 1) * SEQ + m]     = acc[mi][nj][1] + b1;
            g_pT[(size_t)n       * SEQ + m + 8] = acc[mi][nj][2] + b0;
            g_pT[(size_t)(n + 1) * SEQ + m + 8] = acc[mi][nj][3] + b1;
        }
    }
}

// ============== Fused transform + spring scatter ===================
// One thread per (t0, imu) site. Warp-private volatile f32x2 smem
// windows: slot l+t holds (osc1_sum, osc2_sum); RMW is LDS.64 +
// add.f32x2 with the packed Ui + STS.64 (3 issues/step, no unpack).
// Lane i at step t hits slot i+t: distinct within lockstep warp;
// volatile forbids cross-iteration LDS batching.
__global__ __launch_bounds__(256) void spring_kernel(float* __restrict__ out) {
    __shared__ __align__(8) float2 buf[8][336];
    int tid = threadIdx.x;
    int imu = blockIdx.y;
    int c0  = blockIdx.x * 256;
    int t0  = c0 + tid;

    for (int i = tid; i < 8 * 336; i += 256) ((float2*)buf)[i] = make_float2(0.f, 0.f);

    // ---- coalesced param loads from transposed GEMM output ----
    const float* col = g_pT + (size_t)imu * SEQ + t0;   // stride PLANE per noise row
    float p0  = col[0*PLANE],  p1  = col[1*PLANE],  p2  = col[2*PLANE],  p3 = col[3*PLANE];
    float p4  = col[4*PLANE],  p5  = col[5*PLANE],  p6  = col[6*PLANE],  p7 = col[7*PLANE];
    float p8  = col[8*PLANE],  p9  = col[9*PLANE],  p10 = col[10*PLANE], p11 = col[11*PLANE];

    // ---- direct output channels ----
    size_t ob = (size_t)imu * SEQ + t0;
    out[1 * PLANE + ob] = p8;
    out[2 * PLANE + ob] = softplusf(p9);
    out[3 * PLANE + ob] = p10;
    out[4 * PLANE + ob] = softplusf(p11);

    // ---- oscillator params: omega = sqrt(4k-d^2)/2 == sqrt(softplus(p0)) ----
    float om1 = sqrtf(softplusf(p0));
    float e1  = expf(-0.5f * softplusf(p1));
    float om2 = sqrtf(softplusf(p2));
    float e2  = expf(-0.5f * softplusf(p3));
    float sph1, cph1; sincosf(p6, &sph1, &cph1);
    float sph2, cph2; sincosf(p7, &sph2, &cph2);
    float so1, co1;   sincosf(om1, &so1, &co1);
    float so2, co2;   sincosf(om2, &so2, &co2);

    // pack both oscillators into f32x2 lanes
    ull Ur  = fpack2(p4 * cph1, p5 * cph2);
    ull Ui  = fpack2(p4 * sph1, p5 * sph2);
    ull Rr  = fpack2(e1 * co1,  e2 * co2);
    ull Ri  = fpack2(e1 * so1,  e2 * so2);
    ull Rin = fpack2(-e1 * so1, -e2 * so2);

    __syncthreads();

    uint32_t wb = smem_to_u32(&buf[tid >> 5][tid & 31]);   // slot l, advances by 8B/step

    #pragma unroll 8
    for (int t = 0; t < TSTEPS; ++t) {
        sts64_vol(wb, fadd2(lds64_vol(wb), Ui));
        wb += 8;
        ull t1 = fmul2(Ui, Rin);
        ull t2 = fmul2(Ui, Rr);
        ull nr = ffma2(Ur, Rr, t1);
        ull ni = ffma2(Ur, Ri, t2);
        Ur = nr; Ui = ni;
    }
    __syncthreads();

    // merge 8 overlapping warp windows -> block output span [c0, c0+554]
    for (int o = tid; o < 555; o += 256) {
        float v = 0.f;
        #pragma unroll
        for (int w = 0; w < 8; ++w) {
            int idx = o - (w << 5);
            if (idx >= 0 && idx <= 330) {
                float2 b = buf[w][idx];
                v += b.x + b.y;
            }
        }
        int pos = c0 + o;
        if (pos < SEQ) atomicAdd(out + (size_t)imu * SEQ + pos, v);
    }
}

// =========================== launch ================================
extern "C" void kernel_launch(void* const* d_in, const int* in_sizes, int n_in,
                              void* d_out, int out_size) {
    const float* hs    = (const float*)d_in[0];
    const float* gamma = (const float*)d_in[1];
    const float* beta  = (const float*)d_in[2];
    const float* W     = (const float*)d_in[3];
    const float* b     = (const float*)d_in[4];
    float* out = (float*)d_out;

    cudaFuncSetAttribute(gemm_kernel, cudaFuncAttributeMaxDynamicSharedMemorySize, SMEM_TOT);

    zero_kernel<<<PLANE / 1024, 256>>>(out);                       // #1
    prep_kernel<<<SEQ + 864, 256>>>(hs, gamma, beta, W);           // #2 (LN + W^T)
    gemm_kernel<<<dim3(NOUT / BN, SEQ / BM), 256, SMEM_TOT>>>(b);  // #3
    spring_kernel<<<dim3(SEQ / 256, NIMU), 256>>>(out);            // #4 (ncu target)
}